// round 1
// baseline (speedup 1.0000x reference)
#include <cuda_runtime.h>

#define BATCH 4
#define CH    256
#define NPIX  4096
#define TQ    64
#define TJ    64
#define KST   260   // padded row stride (floats) for Qs/Ks/Vs
#define PST   68    // padded row stride for Ps
#define NTILE (NPIX / TJ)

__device__ float g_Q[(size_t)BATCH * NPIX * CH];
__device__ float g_K[(size_t)BATCH * NPIX * CH];
__device__ float g_V[(size_t)BATCH * NPIX * CH];

// ---------------------------------------------------------------------------
// Projection: out[b][p][o] = sum_c w[o][c] * x[b][c][p] + bias[o]
// x: [B][C][N] (1x1 conv input), w: [O][C], out: token-major [B][N][C]
// 128x128 tile, BK=16, 256 threads, 8x8 register fragments.
// ---------------------------------------------------------------------------
__global__ __launch_bounds__(256) void proj_kernel(
    const float* __restrict__ x, const float* __restrict__ w,
    const float* __restrict__ bias, int which)
{
    __shared__ float As[16][128];
    __shared__ float Bs[16 * 132];

    float* outp = (which == 0) ? g_Q : (which == 1) ? g_K : g_V;

    const int b  = blockIdx.z;
    const int p0 = blockIdx.x * 128;
    const int o0 = blockIdx.y * 128;
    const int t  = threadIdx.x;
    const int tx = t & 15;
    const int ty = t >> 4;

    float acc[8][8];
#pragma unroll
    for (int i = 0; i < 8; ++i)
#pragma unroll
        for (int j = 0; j < 8; ++j) acc[i][j] = 0.f;

    const float* xb = x + (size_t)b * CH * NPIX;

    const int lcc  = t >> 4;          // A tile row (c within chunk)
    const int lcol = (t & 15) * 8;    // A tile col (p)
    const int loo  = t >> 1;          // B tile row (o)
    const int lch  = (t & 1) * 8;     // B tile col base (c within chunk)

    for (int c0 = 0; c0 < CH; c0 += 16) {
        {
            const float* src = xb + (size_t)(c0 + lcc) * NPIX + p0 + lcol;
            float4 v0 = *(const float4*)(src);
            float4 v1 = *(const float4*)(src + 4);
            *(float4*)&As[lcc][lcol]     = v0;
            *(float4*)&As[lcc][lcol + 4] = v1;
        }
        {
            const float* src = w + (size_t)(o0 + loo) * CH + c0 + lch;
            float4 v0 = *(const float4*)(src);
            float4 v1 = *(const float4*)(src + 4);
            Bs[(lch + 0) * 132 + loo] = v0.x;
            Bs[(lch + 1) * 132 + loo] = v0.y;
            Bs[(lch + 2) * 132 + loo] = v0.z;
            Bs[(lch + 3) * 132 + loo] = v0.w;
            Bs[(lch + 4) * 132 + loo] = v1.x;
            Bs[(lch + 5) * 132 + loo] = v1.y;
            Bs[(lch + 6) * 132 + loo] = v1.z;
            Bs[(lch + 7) * 132 + loo] = v1.w;
        }
        __syncthreads();
#pragma unroll
        for (int kk = 0; kk < 16; ++kk) {
            float a[8], bb[8];
            *(float4*)(a)      = *(float4*)&As[kk][ty * 8];
            *(float4*)(a + 4)  = *(float4*)&As[kk][ty * 8 + 4];
            *(float4*)(bb)     = *(float4*)&Bs[kk * 132 + tx * 8];
            *(float4*)(bb + 4) = *(float4*)&Bs[kk * 132 + tx * 8 + 4];
#pragma unroll
            for (int i = 0; i < 8; ++i)
#pragma unroll
                for (int j = 0; j < 8; ++j)
                    acc[i][j] += a[i] * bb[j];
        }
        __syncthreads();
    }

    float bv[8];
#pragma unroll
    for (int j = 0; j < 8; ++j) bv[j] = bias[o0 + tx * 8 + j];
#pragma unroll
    for (int i = 0; i < 8; ++i) {
        float* dst = outp + ((size_t)b * NPIX + p0 + ty * 8 + i) * CH + o0 + tx * 8;
        float4 r0 = make_float4(acc[i][0] + bv[0], acc[i][1] + bv[1],
                                acc[i][2] + bv[2], acc[i][3] + bv[3]);
        float4 r1 = make_float4(acc[i][4] + bv[4], acc[i][5] + bv[5],
                                acc[i][6] + bv[6], acc[i][7] + bv[7]);
        *(float4*)dst       = r0;
        *(float4*)(dst + 4) = r1;
    }
}

// ---------------------------------------------------------------------------
// Fused attention + LayerNorm.
// One block = 64 queries of one batch. Loops over 64 key tiles of 64 keys.
// Softmax is COMPLETE within each 64-key tile (reference softmaxes over the
// last spatial axis j only), so no online-softmax carry state is needed.
// ---------------------------------------------------------------------------
__global__ __launch_bounds__(256, 1) void attn_kernel(
    const float* __restrict__ lnw, const float* __restrict__ lnb,
    float* __restrict__ out)
{
    extern __shared__ float sm[];
    float* Qs = sm;                 // TQ * KST
    float* Ks = Qs + TQ * KST;      // TJ * KST
    float* Vs = Ks + TJ * KST;      // TJ * KST
    float* Ps = Vs + TJ * KST;      // TQ * PST

    const int b  = blockIdx.y;
    const int p0 = blockIdx.x * TQ;
    const int t  = threadIdx.x;

    const float* Qg = g_Q + ((size_t)b * NPIX + p0) * CH;
    const float* Kg = g_K + (size_t)b * NPIX * CH;
    const float* Vg = g_V + (size_t)b * NPIX * CH;

    // Load Q tile (64 x 256) once
    for (int i = t; i < TQ * 64; i += 256) {
        int row = i >> 6, c4 = (i & 63) << 2;
        *(float4*)&Qs[row * KST + c4] = *(const float4*)(Qg + (size_t)row * CH + c4);
    }

    const int tq  = t >> 4;            // S-stage: query group (x4)
    const int tj  = t & 15;            // S-stage: key group (stride-16 x4)
    const int qav = t >> 2;            // AV-stage: query
    const int cg  = (t & 3) << 6;      // AV-stage: channel base (0/64/128/192)
    const int rot = (t & 3) << 1;      // bank-rotation to avoid V-read conflicts

    float o[64];
#pragma unroll
    for (int i = 0; i < 64; ++i) o[i] = 0.f;

    for (int tile = 0; tile < NTILE; ++tile) {
        __syncthreads();  // prev AV done (and Q load, first iter)
        const float* kb = Kg + (size_t)tile * TJ * CH;
        const float* vb = Vg + (size_t)tile * TJ * CH;
        for (int i = t; i < TJ * 64; i += 256) {
            int row = i >> 6, c4 = (i & 63) << 2;
            *(float4*)&Ks[row * KST + c4] = *(const float4*)(kb + (size_t)row * CH + c4);
            *(float4*)&Vs[row * KST + c4] = *(const float4*)(vb + (size_t)row * CH + c4);
        }
        __syncthreads();

        // S = Q K^T   (4x4 fragment per thread over 16x16 thread grid)
        float acc[4][4];
#pragma unroll
        for (int i = 0; i < 4; ++i)
#pragma unroll
            for (int j = 0; j < 4; ++j) acc[i][j] = 0.f;

#pragma unroll 4
        for (int c4 = 0; c4 < 64; ++c4) {
            float4 qv[4], kv[4];
#pragma unroll
            for (int i = 0; i < 4; ++i)
                qv[i] = *(const float4*)&Qs[(tq * 4 + i) * KST + c4 * 4];
#pragma unroll
            for (int j = 0; j < 4; ++j)
                kv[j] = *(const float4*)&Ks[(tj + 16 * j) * KST + c4 * 4];
#pragma unroll
            for (int i = 0; i < 4; ++i)
#pragma unroll
                for (int j = 0; j < 4; ++j) {
                    acc[i][j] += qv[i].x * kv[j].x;
                    acc[i][j] += qv[i].y * kv[j].y;
                    acc[i][j] += qv[i].z * kv[j].z;
                    acc[i][j] += qv[i].w * kv[j].w;
                }
        }

        // Complete softmax within this 64-key tile (row-wise over j)
#pragma unroll
        for (int i = 0; i < 4; ++i) {
            const int q = tq * 4 + i;
            float mx = fmaxf(fmaxf(acc[i][0], acc[i][1]), fmaxf(acc[i][2], acc[i][3]));
#pragma unroll
            for (int off = 8; off > 0; off >>= 1)
                mx = fmaxf(mx, __shfl_xor_sync(0xffffffffu, mx, off, 16));
            float pv[4], sum = 0.f;
#pragma unroll
            for (int j = 0; j < 4; ++j) {
                pv[j] = __expf(acc[i][j] - mx);
                sum += pv[j];
            }
#pragma unroll
            for (int off = 8; off > 0; off >>= 1)
                sum += __shfl_xor_sync(0xffffffffu, sum, off, 16);
            const float inv = __fdividef(1.f, sum);
#pragma unroll
            for (int j = 0; j < 4; ++j)
                Ps[q * PST + tj + 16 * j] = pv[j] * inv;
        }
        __syncthreads();

        // O += P * V   (each thread: one query x 64 channels)
        {
            const float* prow = Ps + qav * PST;
#pragma unroll 2
            for (int j = 0; j < TJ; ++j) {
                const float pw = prow[j];
                const float* vr = Vs + j * KST + cg;
#pragma unroll
                for (int ii = 0; ii < 16; ++ii) {
                    const int c4 = (ii + rot) & 15;   // rotated smem read order
                    float4 vv = *(const float4*)(vr + c4 * 4);
                    o[ii * 4 + 0] += pw * vv.x;
                    o[ii * 4 + 1] += pw * vv.y;
                    o[ii * 4 + 2] += pw * vv.z;
                    o[ii * 4 + 3] += pw * vv.w;
                }
            }
        }
    }

    // LayerNorm over channels (4 threads per query hold 64 channels each)
    float s1 = 0.f, s2 = 0.f;
#pragma unroll
    for (int i = 0; i < 64; ++i) { s1 += o[i]; s2 += o[i] * o[i]; }
    s1 += __shfl_xor_sync(0xffffffffu, s1, 1, 4);
    s1 += __shfl_xor_sync(0xffffffffu, s1, 2, 4);
    s2 += __shfl_xor_sync(0xffffffffu, s2, 1, 4);
    s2 += __shfl_xor_sync(0xffffffffu, s2, 2, 4);
    const float mean = s1 * (1.f / 256.f);
    const float var  = s2 * (1.f / 256.f) - mean * mean;
    const float rstd = rsqrtf(var + 1e-5f);

    const int p = p0 + qav;
#pragma unroll
    for (int ii = 0; ii < 16; ++ii) {
        const int c4 = (ii + rot) & 15;   // undo storage rotation: o[ii*4+k] is channel cg + c4*4 + k
#pragma unroll
        for (int k = 0; k < 4; ++k) {
            const int c = cg + c4 * 4 + k;
            out[((size_t)b * CH + c) * NPIX + p] =
                (o[ii * 4 + k] - mean) * rstd * lnw[c] + lnb[c];
        }
    }
}

// ---------------------------------------------------------------------------
extern "C" void kernel_launch(void* const* d_in, const int* in_sizes, int n_in,
                              void* d_out, int out_size)
{
    const float* x1  = (const float*)d_in[0];
    const float* x2  = (const float*)d_in[1];
    const float* qw  = (const float*)d_in[2];
    const float* qb  = (const float*)d_in[3];
    const float* kw  = (const float*)d_in[4];
    const float* kb  = (const float*)d_in[5];
    const float* vw  = (const float*)d_in[6];
    const float* vb  = (const float*)d_in[7];
    const float* lnw = (const float*)d_in[8];
    const float* lnb = (const float*)d_in[9];
    float* out = (float*)d_out;

    dim3 pg(NPIX / 128, CH / 128, BATCH);
    proj_kernel<<<pg, 256>>>(x1, qw, qb, 0);
    proj_kernel<<<pg, 256>>>(x2, kw, kb, 1);
    proj_kernel<<<pg, 256>>>(x2, vw, vb, 2);

    const int smem_bytes = (3 * TQ * KST + TQ * PST) * 4;  // 217088 B
    cudaFuncSetAttribute(attn_kernel, cudaFuncAttributeMaxDynamicSharedMemorySize,
                         smem_bytes);
    attn_kernel<<<dim3(NPIX / TQ, BATCH), 256, smem_bytes>>>(lnw, lnb, out);
}

// round 2
// speedup vs baseline: 1.4424x; 1.4424x over previous
#include <cuda_runtime.h>
#include <cstdint>

#define BATCH 4
#define CH    256
#define NPIX  4096
#define TQ    64
#define TJ    64
#define KST   260   // padded row stride (floats) for Qs/Ks/Vs
#define PST   68    // padded row stride for Ps
#define NTILE (NPIX / TJ)
#define NT    512

__device__ float g_Q[(size_t)BATCH * NPIX * CH];
__device__ float g_K[(size_t)BATCH * NPIX * CH];
__device__ float g_V[(size_t)BATCH * NPIX * CH];

// ---- Blackwell packed fp32x2 helpers -------------------------------------
__device__ __forceinline__ double ffma2(double a, double b, double c) {
    double d;
    asm("fma.rn.f32x2 %0, %1, %2, %3;" : "=d"(d) : "d"(a), "d"(b), "d"(c));
    return d;
}
__device__ __forceinline__ double pack2(float x) {
    double d;
    asm("mov.b64 %0, {%1, %1};" : "=d"(d) : "f"(x));
    return d;
}
__device__ __forceinline__ float2 unpack2(double d) {
    float2 r;
    asm("mov.b64 {%0, %1}, %2;" : "=f"(r.x), "=f"(r.y) : "d"(d));
    return r;
}
#define CP16(dst, src) asm volatile("cp.async.cg.shared.global [%0], [%1], 16;" :: "r"(dst), "l"(src))
#define CP_COMMIT()    asm volatile("cp.async.commit_group;")
#define CP_WAIT(n)     asm volatile("cp.async.wait_group %0;" :: "n"(n))

// ---------------------------------------------------------------------------
// Projection: out[b][p][o] = sum_c w[o][c] * x[b][c][p] + bias[o]
// ---------------------------------------------------------------------------
__global__ __launch_bounds__(256) void proj_kernel(
    const float* __restrict__ x, const float* __restrict__ w,
    const float* __restrict__ bias, int which)
{
    __shared__ float As[16][128];
    __shared__ float Bs[16 * 132];

    float* outp = (which == 0) ? g_Q : (which == 1) ? g_K : g_V;

    const int b  = blockIdx.z;
    const int p0 = blockIdx.x * 128;
    const int o0 = blockIdx.y * 128;
    const int t  = threadIdx.x;
    const int tx = t & 15;
    const int ty = t >> 4;

    float acc[8][8];
#pragma unroll
    for (int i = 0; i < 8; ++i)
#pragma unroll
        for (int j = 0; j < 8; ++j) acc[i][j] = 0.f;

    const float* xb = x + (size_t)b * CH * NPIX;

    const int lcc  = t >> 4;
    const int lcol = (t & 15) * 8;
    const int loo  = t >> 1;
    const int lch  = (t & 1) * 8;

    for (int c0 = 0; c0 < CH; c0 += 16) {
        {
            const float* src = xb + (size_t)(c0 + lcc) * NPIX + p0 + lcol;
            float4 v0 = *(const float4*)(src);
            float4 v1 = *(const float4*)(src + 4);
            *(float4*)&As[lcc][lcol]     = v0;
            *(float4*)&As[lcc][lcol + 4] = v1;
        }
        {
            const float* src = w + (size_t)(o0 + loo) * CH + c0 + lch;
            float4 v0 = *(const float4*)(src);
            float4 v1 = *(const float4*)(src + 4);
            Bs[(lch + 0) * 132 + loo] = v0.x;
            Bs[(lch + 1) * 132 + loo] = v0.y;
            Bs[(lch + 2) * 132 + loo] = v0.z;
            Bs[(lch + 3) * 132 + loo] = v0.w;
            Bs[(lch + 4) * 132 + loo] = v1.x;
            Bs[(lch + 5) * 132 + loo] = v1.y;
            Bs[(lch + 6) * 132 + loo] = v1.z;
            Bs[(lch + 7) * 132 + loo] = v1.w;
        }
        __syncthreads();
#pragma unroll
        for (int kk = 0; kk < 16; ++kk) {
            float a[8], bb[8];
            *(float4*)(a)      = *(float4*)&As[kk][ty * 8];
            *(float4*)(a + 4)  = *(float4*)&As[kk][ty * 8 + 4];
            *(float4*)(bb)     = *(float4*)&Bs[kk * 132 + tx * 8];
            *(float4*)(bb + 4) = *(float4*)&Bs[kk * 132 + tx * 8 + 4];
#pragma unroll
            for (int i = 0; i < 8; ++i)
#pragma unroll
                for (int j = 0; j < 8; ++j)
                    acc[i][j] += a[i] * bb[j];
        }
        __syncthreads();
    }

    float bv[8];
#pragma unroll
    for (int j = 0; j < 8; ++j) bv[j] = bias[o0 + tx * 8 + j];
#pragma unroll
    for (int i = 0; i < 8; ++i) {
        float* dst = outp + ((size_t)b * NPIX + p0 + ty * 8 + i) * CH + o0 + tx * 8;
        float4 r0 = make_float4(acc[i][0] + bv[0], acc[i][1] + bv[1],
                                acc[i][2] + bv[2], acc[i][3] + bv[3]);
        float4 r1 = make_float4(acc[i][4] + bv[4], acc[i][5] + bv[5],
                                acc[i][6] + bv[6], acc[i][7] + bv[7]);
        *(float4*)dst       = r0;
        *(float4*)(dst + 4) = r1;
    }
}

// ---------------------------------------------------------------------------
// Fused attention + LayerNorm. 512 threads, f32x2 math, cp.async pipeline.
// ---------------------------------------------------------------------------
__global__ __launch_bounds__(NT, 1) void attn_kernel(
    const float* __restrict__ lnw, const float* __restrict__ lnb,
    float* __restrict__ out)
{
    extern __shared__ float sm[];
    float* Qs = sm;                 // TQ * KST
    float* Ks = Qs + TQ * KST;      // TJ * KST
    float* Vs = Ks + TJ * KST;      // TJ * KST
    float* Ps = Vs + TJ * KST;      // TQ * PST

    const int b  = blockIdx.y;
    const int p0 = blockIdx.x * TQ;
    const int t  = threadIdx.x;

    const float* Qg = g_Q + ((size_t)b * NPIX + p0) * CH;
    const float* Kg = g_K + (size_t)b * NPIX * CH;
    const float* Vg = g_V + (size_t)b * NPIX * CH;

    const uint32_t Ks_a = (uint32_t)__cvta_generic_to_shared(Ks);
    const uint32_t Vs_a = (uint32_t)__cvta_generic_to_shared(Vs);

    // Load Q tile (plain), preload K0/V0 via cp.async
#pragma unroll
    for (int i = 0; i < 8; ++i) {
        int idx = t + NT * i, row = idx >> 6, c4 = (idx & 63) << 2;
        *(float4*)&Qs[row * KST + c4] = *(const float4*)(Qg + (size_t)row * CH + c4);
    }
#pragma unroll
    for (int i = 0; i < 8; ++i) {
        int idx = t + NT * i, row = idx >> 6, c4 = (idx & 63) << 2;
        CP16(Ks_a + (uint32_t)(row * KST + c4) * 4u, Kg + (size_t)row * CH + c4);
    }
    CP_COMMIT();
#pragma unroll
    for (int i = 0; i < 8; ++i) {
        int idx = t + NT * i, row = idx >> 6, c4 = (idx & 63) << 2;
        CP16(Vs_a + (uint32_t)(row * KST + c4) * 4u, Vg + (size_t)row * CH + c4);
    }
    CP_COMMIT();

    const int tq = t >> 4, tj = t & 15;          // S-stage thread grid 32x16
    const int qpart = t >> 5, cpart = t & 31;    // AV-stage thread grid 16x32
    const int cA = cpart * 4, cB = 128 + cpart * 4;

    double av[16];                               // O accum: 4q x (4 c-pairs)
#pragma unroll
    for (int i = 0; i < 16; ++i) av[i] = 0.0;

    for (int tile = 0; tile < NTILE; ++tile) {
        CP_WAIT(1);          // K(tile) complete (V(tile) may still fly)
        __syncthreads();

        // ---- S = Q K^T : 2q x 4j per thread, k paired into f32x2 lanes
        double s2[2][4];
#pragma unroll
        for (int i = 0; i < 2; ++i)
#pragma unroll
            for (int j = 0; j < 4; ++j) s2[i][j] = 0.0;

        const float* q0r = Qs + (2 * tq) * KST;
        const float* q1r = q0r + KST;
#pragma unroll 8
        for (int c4 = 0; c4 < 64; ++c4) {
            double2 qa = *(const double2*)(q0r + c4 * 4);
            double2 qb = *(const double2*)(q1r + c4 * 4);
#pragma unroll
            for (int jj = 0; jj < 4; ++jj) {
                double2 kv = *(const double2*)(Ks + (tj + 16 * jj) * KST + c4 * 4);
                s2[0][jj] = ffma2(qa.x, kv.x, s2[0][jj]);
                s2[0][jj] = ffma2(qa.y, kv.y, s2[0][jj]);
                s2[1][jj] = ffma2(qb.x, kv.x, s2[1][jj]);
                s2[1][jj] = ffma2(qb.y, kv.y, s2[1][jj]);
            }
        }

        // ---- softmax over the 64-key tile (complete per reference)
#pragma unroll
        for (int i = 0; i < 2; ++i) {
            float s[4];
#pragma unroll
            for (int j = 0; j < 4; ++j) { float2 u = unpack2(s2[i][j]); s[j] = u.x + u.y; }
            float mx = fmaxf(fmaxf(s[0], s[1]), fmaxf(s[2], s[3]));
#pragma unroll
            for (int off = 8; off > 0; off >>= 1)
                mx = fmaxf(mx, __shfl_xor_sync(0xffffffffu, mx, off, 16));
            float sum = 0.f, pv[4];
#pragma unroll
            for (int j = 0; j < 4; ++j) { pv[j] = __expf(s[j] - mx); sum += pv[j]; }
#pragma unroll
            for (int off = 8; off > 0; off >>= 1)
                sum += __shfl_xor_sync(0xffffffffu, sum, off, 16);
            const float inv = __fdividef(1.f, sum);
#pragma unroll
            for (int j = 0; j < 4; ++j)
                Ps[(2 * tq + i) * PST + tj + 16 * j] = pv[j] * inv;
        }

        CP_WAIT(0);          // V(tile) complete
        __syncthreads();     // Ks free; Vs + Ps visible to all

        if (tile < NTILE - 1) {   // K(t+1) load overlaps AV(t)
            const float* kb = Kg + (size_t)(tile + 1) * TJ * CH;
#pragma unroll
            for (int i = 0; i < 8; ++i) {
                int idx = t + NT * i, row = idx >> 6, c4 = (idx & 63) << 2;
                CP16(Ks_a + (uint32_t)(row * KST + c4) * 4u, kb + (size_t)row * CH + c4);
            }
            CP_COMMIT();
        }

        // ---- O += P V : 4q x 8c per thread, c paired into f32x2 lanes
        const float* prow = Ps + (qpart * 4) * PST;
#pragma unroll 2
        for (int j4 = 0; j4 < 16; ++j4) {
            float4 pv0 = *(const float4*)(prow + 0 * PST + j4 * 4);
            float4 pv1 = *(const float4*)(prow + 1 * PST + j4 * 4);
            float4 pv2 = *(const float4*)(prow + 2 * PST + j4 * 4);
            float4 pv3 = *(const float4*)(prow + 3 * PST + j4 * 4);
#pragma unroll
            for (int jj = 0; jj < 4; ++jj) {
                const float* vr = Vs + (j4 * 4 + jj) * KST;
                double2 va = *(const double2*)(vr + cA);
                double2 vb = *(const double2*)(vr + cB);
                double pd0 = pack2(((const float*)&pv0)[jj]);
                double pd1 = pack2(((const float*)&pv1)[jj]);
                double pd2 = pack2(((const float*)&pv2)[jj]);
                double pd3 = pack2(((const float*)&pv3)[jj]);
                av[0]  = ffma2(pd0, va.x, av[0]);
                av[1]  = ffma2(pd0, va.y, av[1]);
                av[2]  = ffma2(pd0, vb.x, av[2]);
                av[3]  = ffma2(pd0, vb.y, av[3]);
                av[4]  = ffma2(pd1, va.x, av[4]);
                av[5]  = ffma2(pd1, va.y, av[5]);
                av[6]  = ffma2(pd1, vb.x, av[6]);
                av[7]  = ffma2(pd1, vb.y, av[7]);
                av[8]  = ffma2(pd2, va.x, av[8]);
                av[9]  = ffma2(pd2, va.y, av[9]);
                av[10] = ffma2(pd2, vb.x, av[10]);
                av[11] = ffma2(pd2, vb.y, av[11]);
                av[12] = ffma2(pd3, va.x, av[12]);
                av[13] = ffma2(pd3, va.y, av[13]);
                av[14] = ffma2(pd3, vb.x, av[14]);
                av[15] = ffma2(pd3, vb.y, av[15]);
            }
        }
        __syncthreads();     // all threads done reading Vs

        if (tile < NTILE - 1) {   // V(t+1) load overlaps S(t+1)
            const float* vbg = Vg + (size_t)(tile + 1) * TJ * CH;
#pragma unroll
            for (int i = 0; i < 8; ++i) {
                int idx = t + NT * i, row = idx >> 6, c4 = (idx & 63) << 2;
                CP16(Vs_a + (uint32_t)(row * KST + c4) * 4u, vbg + (size_t)row * CH + c4);
            }
            CP_COMMIT();
        }
    }

    // ---- LayerNorm over channels (one query's 256 ch spread over 32 lanes)
    const float rn = 1.f / 256.f;
#pragma unroll
    for (int qq = 0; qq < 4; ++qq) {
        float o[8];
#pragma unroll
        for (int pp = 0; pp < 4; ++pp) {
            float2 u = unpack2(av[qq * 4 + pp]);
            o[pp * 2] = u.x; o[pp * 2 + 1] = u.y;
        }
        float s1 = 0.f, s2v = 0.f;
#pragma unroll
        for (int i = 0; i < 8; ++i) { s1 += o[i]; s2v += o[i] * o[i]; }
#pragma unroll
        for (int off = 16; off > 0; off >>= 1) {
            s1  += __shfl_xor_sync(0xffffffffu, s1, off);
            s2v += __shfl_xor_sync(0xffffffffu, s2v, off);
        }
        const float mean = s1 * rn;
        const float var  = s2v * rn - mean * mean;
        const float rstd = rsqrtf(var + 1e-5f);
        const int p = p0 + qpart * 4 + qq;
#pragma unroll
        for (int k = 0; k < 4; ++k) {
            int c = cA + k;      // o[0..3] = channels cA..cA+3 (va.x/va.y pairs)
            out[((size_t)b * CH + c) * NPIX + p] = (o[k] - mean) * rstd * lnw[c] + lnb[c];
            c = cB + k;          // o[4..7] = channels cB..cB+3
            out[((size_t)b * CH + c) * NPIX + p] = (o[4 + k] - mean) * rstd * lnw[c] + lnb[c];
        }
    }
}

// ---------------------------------------------------------------------------
extern "C" void kernel_launch(void* const* d_in, const int* in_sizes, int n_in,
                              void* d_out, int out_size)
{
    const float* x1  = (const float*)d_in[0];
    const float* x2  = (const float*)d_in[1];
    const float* qw  = (const float*)d_in[2];
    const float* qb  = (const float*)d_in[3];
    const float* kw  = (const float*)d_in[4];
    const float* kb  = (const float*)d_in[5];
    const float* vw  = (const float*)d_in[6];
    const float* vb  = (const float*)d_in[7];
    const float* lnw = (const float*)d_in[8];
    const float* lnb = (const float*)d_in[9];
    float* out = (float*)d_out;

    dim3 pg(NPIX / 128, CH / 128, BATCH);
    proj_kernel<<<pg, 256>>>(x1, qw, qb, 0);
    proj_kernel<<<pg, 256>>>(x2, kw, kb, 1);
    proj_kernel<<<pg, 256>>>(x2, vw, vb, 2);

    const int smem_bytes = (3 * TQ * KST + TQ * PST) * 4;  // 217088 B
    cudaFuncSetAttribute(attn_kernel, cudaFuncAttributeMaxDynamicSharedMemorySize,
                         smem_bytes);
    attn_kernel<<<dim3(NPIX / TQ, BATCH), NT, smem_bytes>>>(lnw, lnb, out);
}